// round 3
// baseline (speedup 1.0000x reference)
#include <cuda_runtime.h>

#define N_MAX 100000
#define E_MAX 1200000
#define DIN   64
#define DHID  64
#define DOUT  34
#define SCAN_BS 512
#define NB_MAX ((N_MAX + SCAN_BS - 1) / SCAN_BS)

// ---- scratch (allocation-free: __device__ globals) ----
__device__ int   g_deg [N_MAX];
__device__ float g_dinv[N_MAX];
__device__ int   g_off [N_MAX + 1];       // CSR offsets (real in-edges per dst)
__device__ int   g_cur [N_MAX];           // fill cursors
__device__ int   g_bsum[NB_MAX];          // scan block sums
__device__ int2  g_edge[E_MAX];           // CSR: (src, bits(dinv[src])) per edge
__device__ float g_s   [(size_t)N_MAX * DIN];   // pre-aggregated + self input
__device__ float g_hw  [(size_t)N_MAX * DOUT];  // softmax(relu(h)) @ W2

// ---------------------------------------------------------------------------
__global__ void k_deg_init(int n) {
    int i = blockIdx.x * blockDim.x + threadIdx.x;
    if (i < n) g_deg[i] = 1;   // self-loop contributes 1
}

__global__ void k_deg_count(const int* __restrict__ dst, int e) {
    int i = blockIdx.x * blockDim.x + threadIdx.x;
    if (i < e) atomicAdd(&g_deg[dst[i]], 1);
}

// ---- exclusive scan of (deg-1) into g_off; also computes dinv ------------
__global__ void k_scan1(int n) {
    __shared__ int sh[SCAN_BS];
    int i = blockIdx.x * SCAN_BS + threadIdx.x;
    int v = (i < n) ? (g_deg[i] - 1) : 0;
    if (i < n) g_dinv[i] = rsqrtf((float)(v + 1));
    sh[threadIdx.x] = v;
    __syncthreads();
    for (int off = 1; off < SCAN_BS; off <<= 1) {
        int t = (threadIdx.x >= off) ? sh[threadIdx.x - off] : 0;
        __syncthreads();
        sh[threadIdx.x] += t;
        __syncthreads();
    }
    if (i < n) g_off[i] = sh[threadIdx.x] - v;
    if (threadIdx.x == SCAN_BS - 1) g_bsum[blockIdx.x] = sh[threadIdx.x];
}

__global__ void k_scan2(int nb, int n) {
    if (threadIdx.x == 0 && blockIdx.x == 0) {
        int run = 0;
        for (int b = 0; b < nb; b++) { int t = g_bsum[b]; g_bsum[b] = run; run += t; }
        g_off[n] = run;
    }
}

__global__ void k_scan3(int n) {
    int i = blockIdx.x * blockDim.x + threadIdx.x;
    if (i < n) {
        int o = g_off[i] + g_bsum[i / SCAN_BS];
        g_off[i] = o;
        g_cur[i] = o;
    }
}

__global__ void k_fill(const int* __restrict__ src, const int* __restrict__ dst, int e) {
    int i = blockIdx.x * blockDim.x + threadIdx.x;
    if (i < e) {
        int s = src[i];
        int pos = atomicAdd(&g_cur[dst[i]], 1);
        g_edge[pos] = make_int2(s, __float_as_int(g_dinv[s]));
    }
}

// ---------------------------------------------------------------------------
// Pre-GEMM aggregation of x: g_s[i] = dinv[i]*(sum_e dinv[src]*x[src] + dinv[i]*x[i])
// Warp per node; two half-warps process independent edge streams (16 lanes x
// float4 = 256B coalesced row reads), manual unroll-2 -> 4 loads in flight.
__global__ void k_aggx(const float* __restrict__ x, int n) {
    int warp = threadIdx.x >> 5, lane = threadIdx.x & 31;
    int node = blockIdx.x * 8 + warp;
    if (node >= n) return;
    int beg = g_off[node], end = g_off[node + 1];
    int half = lane >> 4, sub = lane & 15;

    float4 acc = make_float4(0.f, 0.f, 0.f, 0.f);
    for (int j = beg; j < end; j += 32) {
        int idx = j + lane;
        int2 ed = make_int2(0, 0);
        if (idx < end) ed = g_edge[idx];
        int m  = min(32, end - j);
        int mt = (m + 1) >> 1;       // warp-uniform trip count
        int t  = 0;
        for (; t + 2 <= mt; t += 2) {
            int l0 = 2 * t + half, l1 = l0 + 2;
            int   s0 = __shfl_sync(0xffffffffu, ed.x, l0);
            float w0 = __int_as_float(__shfl_sync(0xffffffffu, ed.y, l0));
            int   s1 = __shfl_sync(0xffffffffu, ed.x, l1);
            float w1 = __int_as_float(__shfl_sync(0xffffffffu, ed.y, l1));
            if (l0 < m) {
                float4 v = *(const float4*)(x + (size_t)s0 * DIN + sub * 4);
                acc.x = fmaf(w0, v.x, acc.x); acc.y = fmaf(w0, v.y, acc.y);
                acc.z = fmaf(w0, v.z, acc.z); acc.w = fmaf(w0, v.w, acc.w);
            }
            if (l1 < m) {
                float4 v = *(const float4*)(x + (size_t)s1 * DIN + sub * 4);
                acc.x = fmaf(w1, v.x, acc.x); acc.y = fmaf(w1, v.y, acc.y);
                acc.z = fmaf(w1, v.z, acc.z); acc.w = fmaf(w1, v.w, acc.w);
            }
        }
        for (; t < mt; t++) {
            int l0 = 2 * t + half;
            int   s0 = __shfl_sync(0xffffffffu, ed.x, l0);
            float w0 = __int_as_float(__shfl_sync(0xffffffffu, ed.y, l0));
            if (l0 < m) {
                float4 v = *(const float4*)(x + (size_t)s0 * DIN + sub * 4);
                acc.x = fmaf(w0, v.x, acc.x); acc.y = fmaf(w0, v.y, acc.y);
                acc.z = fmaf(w0, v.z, acc.z); acc.w = fmaf(w0, v.w, acc.w);
            }
        }
    }
    // combine halves
    acc.x += __shfl_xor_sync(0xffffffffu, acc.x, 16);
    acc.y += __shfl_xor_sync(0xffffffffu, acc.y, 16);
    acc.z += __shfl_xor_sync(0xffffffffu, acc.z, 16);
    acc.w += __shfl_xor_sync(0xffffffffu, acc.w, 16);
    if (half == 0) {
        float dn = g_dinv[node];
        float4 xv = *(const float4*)(x + (size_t)node * DIN + sub * 4);
        float4 s;
        s.x = dn * fmaf(dn, xv.x, acc.x);
        s.y = dn * fmaf(dn, xv.y, acc.y);
        s.z = dn * fmaf(dn, xv.z, acc.z);
        s.w = dn * fmaf(dn, xv.w, acc.w);
        *(float4*)(g_s + (size_t)node * DIN + sub * 4) = s;
    }
}

// ---------------------------------------------------------------------------
// Fused: h = g_s @ W1 + b1 ; p = softmax(relu(h)) ; hw = p @ W2 ;
// out init = b2 + dinv^2 * hw. Warp handles 4 rows; 2 cols/lane tile.
__global__ void k_fused(const float* __restrict__ W1, const float* __restrict__ b1,
                        const float* __restrict__ W2, const float* __restrict__ b2,
                        float* __restrict__ out, int n) {
    __shared__ float W1s[DIN * DHID];       // 16 KB
    __shared__ float W2s[DHID * DOUT];      // 8.5 KB
    __shared__ float buf[8][4][DHID];       // 8 KB: xs then ps
    for (int i = threadIdx.x; i < DIN * DHID; i += blockDim.x)  W1s[i] = W1[i];
    for (int i = threadIdx.x; i < DHID * DOUT; i += blockDim.x) W2s[i] = W2[i];
    __syncthreads();

    int warp = threadIdx.x >> 5, lane = threadIdx.x & 31;
    int row0 = blockIdx.x * 32 + warp * 4;

    // stage input rows
#pragma unroll
    for (int r = 0; r < 4; r++) {
        int row = row0 + r;
        float2 xv = make_float2(0.f, 0.f);
        if (row < n) xv = *(const float2*)(g_s + (size_t)row * DIN + lane * 2);
        buf[warp][r][lane * 2]     = xv.x;
        buf[warp][r][lane * 2 + 1] = xv.y;
    }
    __syncwarp();

    // GEMM1
    float2 a[4];
#pragma unroll
    for (int r = 0; r < 4; r++) a[r] = make_float2(0.f, 0.f);
#pragma unroll
    for (int k = 0; k < DIN; k++) {
        float2 w = *(const float2*)(W1s + k * DHID + lane * 2);
#pragma unroll
        for (int r = 0; r < 4; r++) {
            float xk = buf[warp][r][k];
            a[r].x = fmaf(xk, w.x, a[r].x);
            a[r].y = fmaf(xk, w.y, a[r].y);
        }
    }
    __syncwarp();   // done reading buf as xs

    // bias + relu + softmax -> p into buf
    float2 bb = *(const float2*)(b1 + lane * 2);
#pragma unroll
    for (int r = 0; r < 4; r++) {
        float v0 = fmaxf(a[r].x + bb.x, 0.f);
        float v1 = fmaxf(a[r].y + bb.y, 0.f);
        float m = fmaxf(v0, v1);
#pragma unroll
        for (int off = 16; off; off >>= 1)
            m = fmaxf(m, __shfl_xor_sync(0xffffffffu, m, off));
        float e0 = __expf(v0 - m), e1 = __expf(v1 - m);
        float ssum = e0 + e1;
#pragma unroll
        for (int off = 16; off; off >>= 1)
            ssum += __shfl_xor_sync(0xffffffffu, ssum, off);
        float inv = 1.0f / ssum;
        buf[warp][r][lane * 2]     = e0 * inv;
        buf[warp][r][lane * 2 + 1] = e1 * inv;
    }
    __syncwarp();

    // GEMM2
    int  c2   = lane + 32;
    bool has2 = (c2 < DOUT);
    int  c2c  = has2 ? c2 : (DOUT - 1);
    float a0[4] = {0.f, 0.f, 0.f, 0.f};
    float a1[4] = {0.f, 0.f, 0.f, 0.f};
#pragma unroll
    for (int k = 0; k < DHID; k++) {
        float w0 = W2s[k * DOUT + lane];
        float w1 = W2s[k * DOUT + c2c];
#pragma unroll
        for (int r = 0; r < 4; r++) {
            float pk = buf[warp][r][k];
            a0[r] = fmaf(pk, w0, a0[r]);
            a1[r] = fmaf(pk, w1, a1[r]);
        }
    }

#pragma unroll
    for (int r = 0; r < 4; r++) {
        int row = row0 + r;
        if (row >= n) break;
        float s = g_dinv[row]; s *= s;
        size_t oo = (size_t)row * DOUT;
        g_hw[oo + lane] = a0[r];
        out [oo + lane] = fmaf(s, a0[r], b2[lane]);
        if (has2) {
            g_hw[oo + c2] = a1[r];
            out [oo + c2] = fmaf(s, a1[r], b2[c2]);
        }
    }
}

// ---------------------------------------------------------------------------
// Layer-2 aggregation of g_hw (34-wide) into out. Half-warp per edge stream.
__global__ void k_agg2(float* __restrict__ out, int n) {
    int warp = threadIdx.x >> 5, lane = threadIdx.x & 31;
    int node = blockIdx.x * 8 + warp;
    if (node >= n) return;
    int beg = g_off[node], end = g_off[node + 1];
    int half = lane >> 4, sub = lane & 15;

    float2 acc  = make_float2(0.f, 0.f);   // features sub*2, sub*2+1
    float2 accx = make_float2(0.f, 0.f);   // features 32,33 (sub==0 lanes)
    for (int j = beg; j < end; j += 32) {
        int idx = j + lane;
        int2 ed = make_int2(0, 0);
        if (idx < end) ed = g_edge[idx];
        int m  = min(32, end - j);
        int mt = (m + 1) >> 1;
        int t  = 0;
        for (; t + 2 <= mt; t += 2) {
            int l0 = 2 * t + half, l1 = l0 + 2;
            int   s0 = __shfl_sync(0xffffffffu, ed.x, l0);
            float w0 = __int_as_float(__shfl_sync(0xffffffffu, ed.y, l0));
            int   s1 = __shfl_sync(0xffffffffu, ed.x, l1);
            float w1 = __int_as_float(__shfl_sync(0xffffffffu, ed.y, l1));
            if (l0 < m) {
                const float* hp = g_hw + (size_t)s0 * DOUT;
                float2 v = *(const float2*)(hp + sub * 2);
                acc.x = fmaf(w0, v.x, acc.x); acc.y = fmaf(w0, v.y, acc.y);
                if (sub == 0) {
                    float2 u = *(const float2*)(hp + 32);
                    accx.x = fmaf(w0, u.x, accx.x); accx.y = fmaf(w0, u.y, accx.y);
                }
            }
            if (l1 < m) {
                const float* hp = g_hw + (size_t)s1 * DOUT;
                float2 v = *(const float2*)(hp + sub * 2);
                acc.x = fmaf(w1, v.x, acc.x); acc.y = fmaf(w1, v.y, acc.y);
                if (sub == 0) {
                    float2 u = *(const float2*)(hp + 32);
                    accx.x = fmaf(w1, u.x, accx.x); accx.y = fmaf(w1, u.y, accx.y);
                }
            }
        }
        for (; t < mt; t++) {
            int l0 = 2 * t + half;
            int   s0 = __shfl_sync(0xffffffffu, ed.x, l0);
            float w0 = __int_as_float(__shfl_sync(0xffffffffu, ed.y, l0));
            if (l0 < m) {
                const float* hp = g_hw + (size_t)s0 * DOUT;
                float2 v = *(const float2*)(hp + sub * 2);
                acc.x = fmaf(w0, v.x, acc.x); acc.y = fmaf(w0, v.y, acc.y);
                if (sub == 0) {
                    float2 u = *(const float2*)(hp + 32);
                    accx.x = fmaf(w0, u.x, accx.x); accx.y = fmaf(w0, u.y, accx.y);
                }
            }
        }
    }
    acc.x  += __shfl_xor_sync(0xffffffffu, acc.x,  16);
    acc.y  += __shfl_xor_sync(0xffffffffu, acc.y,  16);
    accx.x += __shfl_xor_sync(0xffffffffu, accx.x, 16);
    accx.y += __shfl_xor_sync(0xffffffffu, accx.y, 16);
    if (half == 0) {
        float dn = g_dinv[node];
        size_t oo = (size_t)node * DOUT;
        out[oo + sub * 2]     = fmaf(dn, acc.x, out[oo + sub * 2]);
        out[oo + sub * 2 + 1] = fmaf(dn, acc.y, out[oo + sub * 2 + 1]);
        if (sub == 0) {
            out[oo + 32] = fmaf(dn, accx.x, out[oo + 32]);
            out[oo + 33] = fmaf(dn, accx.y, out[oo + 33]);
        }
    }
}

// ---------------------------------------------------------------------------
extern "C" void kernel_launch(void* const* d_in, const int* in_sizes, int n_in,
                              void* d_out, int out_size) {
    const float* x  = (const float*)d_in[0];
    const int*   ei = (const int*)  d_in[1];
    const float* W1 = (const float*)d_in[2];
    const float* b1 = (const float*)d_in[3];
    const float* W2 = (const float*)d_in[4];
    const float* b2 = (const float*)d_in[5];

    int n = in_sizes[0] / DIN;
    int e = in_sizes[1] / 2;
    const int* src = ei;
    const int* dst = ei + e;
    float* out = (float*)d_out;

    int nb = (n + SCAN_BS - 1) / SCAN_BS;

    k_deg_init <<<(n + 255) / 256, 256>>>(n);
    k_deg_count<<<(e + 255) / 256, 256>>>(dst, e);
    k_scan1<<<nb, SCAN_BS>>>(n);
    k_scan2<<<1, 32>>>(nb, n);
    k_scan3<<<(n + 255) / 256, 256>>>(n);
    k_fill <<<(e + 255) / 256, 256>>>(src, dst, e);

    k_aggx <<<(n + 7) / 8, 256>>>(x, n);
    k_fused<<<(n + 31) / 32, 256>>>(W1, b1, W2, b2, out, n);
    k_agg2 <<<(n + 7) / 8, 256>>>(out, n);
}